// round 1
// baseline (speedup 1.0000x reference)
#include <cuda_runtime.h>
#include <math.h>

#define N_NODES 10000
#define N_EDGES 160000
#define WN 640
#define C110 0.57735026918962576451f   /* 1/sqrt(3) */
#define C111 0.70710678118654752440f   /* 1/sqrt(2) */

// ---------------- device scratch (no runtime allocation allowed) ----------------
__device__ float g_W2kT[WN * 32];
__device__ float g_W2vT[WN * 32];
__device__ float g_q[N_NODES * 40];
__device__ float g_attn[N_EDGES];
__device__ float g_vT[40 * (size_t)N_EDGES];
__device__ int   g_m[N_NODES];
__device__ float g_denom[N_NODES];
__device__ float g_numer[40 * N_NODES];
__device__ float g_pre[40 * N_NODES];
__device__ float g_stats[80];

// monotone float<->int key for atomicMax
__device__ __forceinline__ int fkey(float f) {
    int b = __float_as_int(f);
    return (b >= 0) ? b : (int)(b ^ 0x7FFFFFFF);
}
__device__ __forceinline__ float fdec(int k) {
    return (k >= 0) ? __int_as_float(k) : __int_as_float((int)(k ^ 0x7FFFFFFF));
}

// ---------------- prep kernels ----------------
__global__ void k_init() {
    int i = blockIdx.x * 256 + threadIdx.x;
    if (i < 40 * N_NODES) g_numer[i] = 0.0f;
    if (i < N_NODES) { g_denom[i] = 0.0f; g_m[i] = (int)0x807FFFFFu; /* key(-inf) */ }
    if (i < 80) g_stats[i] = 0.0f;
}

__global__ void k_transpose(const float* __restrict__ kw2, const float* __restrict__ vw2) {
    int i = blockIdx.x * 256 + threadIdx.x;
    if (i < WN * 32) {
        int j = i / WN, c = i % WN;
        g_W2kT[c * 32 + j] = kw2[i];
        g_W2vT[c * 32 + j] = vw2[i];
    }
}

__global__ void k_q(const float* __restrict__ atom, const float* __restrict__ Wqs,
                    const float* __restrict__ Wqv) {
    int t = blockIdx.x * 256 + threadIdx.x;
    if (t >= 40 * N_NODES) return;
    int n = t / 40, f = t % 40;
    const float* a = atom + (size_t)n * 40;
    float acc = 0.0f;
    if (f < 16) {
#pragma unroll
        for (int i = 0; i < 16; i++) acc = fmaf(a[i], Wqs[i * 16 + f], acc);
    } else {
        int o = (f - 16) / 3, d = (f - 16) % 3;
#pragma unroll
        for (int i = 0; i < 8; i++) acc = fmaf(a[16 + i * 3 + d], Wqv[i * 8 + o], acc);
    }
    g_q[t] = acc;
}

// ---------------- fused per-edge kernel helpers ----------------
__device__ __forceinline__ void mlp1(const float* __restrict__ sW1T,
                                     const float* __restrict__ sB1,
                                     const float (&ef)[32], float (&h)[32]) {
#pragma unroll
    for (int l = 0; l < 32; l++) {
        float a = sB1[l];
        const float4* w = (const float4*)(sW1T + l * 32);
#pragma unroll
        for (int j = 0; j < 8; j++) {
            float4 ww = w[j];
            a = fmaf(ef[4 * j + 0], ww.x, a);
            a = fmaf(ef[4 * j + 1], ww.y, a);
            a = fmaf(ef[4 * j + 2], ww.z, a);
            a = fmaf(ef[4 * j + 3], ww.w, a);
        }
        h[l] = fmaxf(a, 0.0f);
    }
}

template <int NC>
__device__ __forceinline__ void gemm_cols(const float* __restrict__ w2blk,
                                          const float* __restrict__ b2blk,
                                          const float (&h)[32], float (&acc)[NC]) {
#pragma unroll
    for (int o = 0; o < NC; o++) {
        float a = b2blk[o];
        const float4* w = (const float4*)(w2blk + o * 32);
#pragma unroll
        for (int j = 0; j < 8; j++) {
            float4 ww = w[j];
            a = fmaf(h[4 * j + 0], ww.x, a);
            a = fmaf(h[4 * j + 1], ww.y, a);
            a = fmaf(h[4 * j + 2], ww.z, a);
            a = fmaf(h[4 * j + 3], ww.w, a);
        }
        acc[o] = a;
    }
}

// Fused MLP2-GEMM + tensor-product fold. Never materializes the 640-vector.
__device__ __forceinline__ void tp_apply(const float* __restrict__ sW2,
                                         const float* __restrict__ sB2,
                                         const float (&h)[32],
                                         const float* __restrict__ cxs,  // smem: [0..15]=x_s, [16..23]=C110*dot
                                         float sh_s, float s0, float s1, float s2,
                                         const float (&xv)[24], const float (&crs)[24],
                                         float (&os)[16], float (&ov)[24]) {
    // block1: w1[16x16] with coef x_s[i]*sh_s -> out_s
#pragma unroll 1
    for (int i = 0; i < 16; i++) {
        float acc[16];
        gemm_cols<16>(sW2 + (i * 16) * 32, sB2 + i * 16, h, acc);
        float ci = cxs[i] * sh_s;
#pragma unroll
        for (int o = 0; o < 16; o++) os[o] = fmaf(ci, acc[o], os[o]);
    }
    // block2: w2[8x16] with coef C110*dot[i] -> out_s
#pragma unroll 1
    for (int i = 0; i < 8; i++) {
        float acc[16];
        gemm_cols<16>(sW2 + (256 + i * 16) * 32, sB2 + 256 + i * 16, h, acc);
        float ci = cxs[16 + i];
#pragma unroll
        for (int o = 0; o < 16; o++) os[o] = fmaf(ci, acc[o], os[o]);
    }
    // block3: w3[16x8], out_v[o][d] += w*x_s[i]*sh_v[d]
#pragma unroll 1
    for (int i = 0; i < 16; i++) {
        float acc[8];
        gemm_cols<8>(sW2 + (384 + i * 8) * 32, sB2 + 384 + i * 8, h, acc);
        float ci = cxs[i];
#pragma unroll
        for (int o = 0; o < 8; o++) {
            float t = ci * acc[o];
            ov[o * 3 + 0] = fmaf(t, s0, ov[o * 3 + 0]);
            ov[o * 3 + 1] = fmaf(t, s1, ov[o * 3 + 1]);
            ov[o * 3 + 2] = fmaf(t, s2, ov[o * 3 + 2]);
        }
    }
    // block4: w4[8x8], out_v[o][d] += w*sh_s*x_v[i][d]  (i unrolled: xv stays in regs)
#pragma unroll
    for (int i = 0; i < 8; i++) {
        float acc[8];
        gemm_cols<8>(sW2 + (512 + i * 8) * 32, sB2 + 512 + i * 8, h, acc);
#pragma unroll
        for (int o = 0; o < 8; o++) {
            float t = sh_s * acc[o];
            ov[o * 3 + 0] = fmaf(t, xv[i * 3 + 0], ov[o * 3 + 0]);
            ov[o * 3 + 1] = fmaf(t, xv[i * 3 + 1], ov[o * 3 + 1]);
            ov[o * 3 + 2] = fmaf(t, xv[i * 3 + 2], ov[o * 3 + 2]);
        }
    }
    // block5: w5[8x8], out_v[o][d] += w*C111*cross[i][d]
#pragma unroll
    for (int i = 0; i < 8; i++) {
        float acc[8];
        gemm_cols<8>(sW2 + (576 + i * 8) * 32, sB2 + 576 + i * 8, h, acc);
#pragma unroll
        for (int o = 0; o < 8; o++) {
            float a = acc[o];
            ov[o * 3 + 0] = fmaf(a, crs[i * 3 + 0], ov[o * 3 + 0]);
            ov[o * 3 + 1] = fmaf(a, crs[i * 3 + 1], ov[o * 3 + 1]);
            ov[o * 3 + 2] = fmaf(a, crs[i * 3 + 2], ov[o * 3 + 2]);
        }
    }
}

// smem layout (floats)
#define SM_W2    0
#define SM_W1K   20480
#define SM_W1V   (SM_W1K + 1024)
#define SM_B1K   (SM_W1V + 1024)
#define SM_B1V   (SM_B1K + 32)
#define SM_B2K   (SM_B1V + 32)
#define SM_B2V   (SM_B2K + 640)
#define SM_COEF  (SM_B2V + 640)
#define SM_TOTAL (SM_COEF + 128 * 25)
#define SMEM_BYTES (SM_TOTAL * 4)

__global__ __launch_bounds__(128, 2) void k_edges(
    const float* __restrict__ atom, const float* __restrict__ ef_g,
    const float* __restrict__ sh_g, const int* __restrict__ eidx,
    const float* __restrict__ kw1, const float* __restrict__ kb1, const float* __restrict__ kb2,
    const float* __restrict__ vw1, const float* __restrict__ vb1, const float* __restrict__ vb2) {
    extern __shared__ float sm[];
    float* sW2 = sm + SM_W2;
    float* sW1k = sm + SM_W1K;
    float* sW1v = sm + SM_W1V;
    float* sB1k = sm + SM_B1K;
    float* sB1v = sm + SM_B1V;
    float* sB2k = sm + SM_B2K;
    float* sB2v = sm + SM_B2V;
    float* sCoef = sm + SM_COEF;
    int tid = threadIdx.x;

    // stage W1 (transposed in-flight) + biases
    for (int i = tid; i < 1024; i += 128) {
        sW1k[(i % 32) * 32 + (i / 32)] = kw1[i];
        sW1v[(i % 32) * 32 + (i / 32)] = vw1[i];
    }
    for (int i = tid; i < 640; i += 128) { sB2k[i] = kb2[i]; sB2v[i] = vb2[i]; }
    if (tid < 32) { sB1k[tid] = kb1[tid]; sB1v[tid] = vb1[tid]; }
    // stage W2k^T
    {
        const float4* src = (const float4*)g_W2kT;
        float4* dst = (float4*)sW2;
        for (int i = tid; i < WN * 8; i += 128) dst[i] = src[i];
    }
    __syncthreads();

    int e = blockIdx.x * 128 + tid;
    bool valid = (e < N_EDGES);
    int ee = valid ? e : 0;

    // edge feature row -> registers
    float ef[32];
    {
        const float4* p = (const float4*)(ef_g + (size_t)ee * 32);
#pragma unroll
        for (int i = 0; i < 8; i++) {
            float4 v = __ldg(p + i);
            ef[4 * i + 0] = v.x; ef[4 * i + 1] = v.y; ef[4 * i + 2] = v.z; ef[4 * i + 3] = v.w;
        }
    }
    float hK[32], hV[32];
    mlp1(sW1k, sB1k, ef, hK);
    mlp1(sW1v, sB1v, ef, hV);

    int dst_n = __ldg(eidx + ee);
    int src_n = __ldg(eidx + N_EDGES + ee);
    float4 sh4 = __ldg(((const float4*)sh_g) + ee);
    float sh_s = sh4.x, s0 = sh4.y, s1 = sh4.z, s2 = sh4.w;

    // gather destination node irreps, build TP coefficients
    float xf[40];
    {
        const float4* p = (const float4*)(atom + (size_t)dst_n * 40);
#pragma unroll
        for (int i = 0; i < 10; i++) {
            float4 v = __ldg(p + i);
            xf[4 * i + 0] = v.x; xf[4 * i + 1] = v.y; xf[4 * i + 2] = v.z; xf[4 * i + 3] = v.w;
        }
    }
    float* cx = sCoef + tid * 25;
#pragma unroll
    for (int i = 0; i < 16; i++) cx[i] = xf[i];
    float xv[24], crs[24];
#pragma unroll
    for (int i = 0; i < 8; i++) {
        float a0 = xf[16 + i * 3 + 0], a1 = xf[16 + i * 3 + 1], a2 = xf[16 + i * 3 + 2];
        xv[i * 3 + 0] = a0; xv[i * 3 + 1] = a1; xv[i * 3 + 2] = a2;
        cx[16 + i] = C110 * (a0 * s0 + a1 * s1 + a2 * s2);
        crs[i * 3 + 0] = C111 * (a1 * s2 - a2 * s1);
        crs[i * 3 + 1] = C111 * (a2 * s0 - a0 * s2);
        crs[i * 3 + 2] = C111 * (a0 * s1 - a1 * s0);
    }

    // ---- k path ----
    float os[16], ov[24];
#pragma unroll
    for (int o = 0; o < 16; o++) os[o] = 0.0f;
#pragma unroll
    for (int t = 0; t < 24; t++) ov[t] = 0.0f;
    tp_apply(sW2, sB2k, hK, cx, sh_s, s0, s1, s2, xv, crs, os, ov);

    float attn = 0.0f;
    {
        const float* q = g_q + (size_t)src_n * 40;
#pragma unroll
        for (int o = 0; o < 16; o++) attn = fmaf(os[o], q[o], attn);
#pragma unroll
        for (int t = 0; t < 24; t++) attn = fmaf(ov[t], q[16 + t], attn);
    }
    if (valid) {
        g_attn[e] = attn;
        atomicMax(&g_m[src_n], fkey(attn));
    }

    // ---- v path (restage W2v^T) ----
    __syncthreads();
    {
        const float4* src = (const float4*)g_W2vT;
        float4* dst = (float4*)sW2;
        for (int i = tid; i < WN * 8; i += 128) dst[i] = src[i];
    }
    __syncthreads();
#pragma unroll
    for (int o = 0; o < 16; o++) os[o] = 0.0f;
#pragma unroll
    for (int t = 0; t < 24; t++) ov[t] = 0.0f;
    tp_apply(sW2, sB2v, hV, cx, sh_s, s0, s1, s2, xv, crs, os, ov);

    if (valid) {
#pragma unroll
        for (int o = 0; o < 16; o++) g_vT[(size_t)o * N_EDGES + e] = os[o];
#pragma unroll
        for (int t = 0; t < 24; t++) g_vT[(size_t)(16 + t) * N_EDGES + e] = ov[t];
    }
}

// ---------------- softmax accumulation ----------------
__global__ void k_soft(const int* __restrict__ eidx) {
    int e = blockIdx.x * 256 + threadIdx.x;
    if (e >= N_EDGES) return;
    int src = eidx[N_EDGES + e];
    float m = fdec(g_m[src]);
    float ex = expf(g_attn[e] - m);
    atomicAdd(&g_denom[src], ex);
#pragma unroll
    for (int f = 0; f < 40; f++) {
        atomicAdd(&g_numer[f * N_NODES + src], ex * g_vT[(size_t)f * N_EDGES + e]);
    }
}

// ---------------- pre-activation + batchnorm stats ----------------
__global__ void k_stats(const float* __restrict__ atom) {
    int f = blockIdx.y;
    int n = blockIdx.x * 256 + threadIdx.x;
    float pre = 0.0f;
    if (n < N_NODES) {
        float den = g_denom[n];
        float upd = (den > 0.0f) ? g_numer[f * N_NODES + n] / den : 0.0f;
        pre = atom[(size_t)n * 40 + f] + upd;
        g_pre[f * N_NODES + n] = pre;
    }
    float s = pre, ss = pre * pre;
    unsigned lane = threadIdx.x & 31, wid = threadIdx.x >> 5;
#pragma unroll
    for (int o = 16; o > 0; o >>= 1) {
        s += __shfl_down_sync(0xFFFFFFFFu, s, o);
        ss += __shfl_down_sync(0xFFFFFFFFu, ss, o);
    }
    __shared__ float rs[8], rss[8];
    if (lane == 0) { rs[wid] = s; rss[wid] = ss; }
    __syncthreads();
    if (threadIdx.x == 0) {
        float S = 0.0f, SS = 0.0f;
#pragma unroll
        for (int w = 0; w < 8; w++) { S += rs[w]; SS += rss[w]; }
        atomicAdd(&g_stats[f], S);
        atomicAdd(&g_stats[40 + f], SS);
    }
}

// ---------------- batchnorm finalize ----------------
__global__ void k_final(const float* __restrict__ bnws, const float* __restrict__ bnbs,
                        const float* __restrict__ bnwv, float* __restrict__ out) {
    int t = blockIdx.x * 256 + threadIdx.x;
    if (t >= 40 * N_NODES) return;
    int n = t / 40, f = t % 40;
    float pre = g_pre[f * N_NODES + n];
    float r;
    if (f < 16) {
        float mu = g_stats[f] * (1.0f / N_NODES);
        float var = g_stats[40 + f] * (1.0f / N_NODES) - mu * mu;
        r = (pre - mu) * rsqrtf(var + 1e-5f) * bnws[f] + bnbs[f];
    } else {
        int i = (f - 16) / 3;
        float nrm = (g_stats[40 + 16 + i * 3 + 0] + g_stats[40 + 16 + i * 3 + 1] +
                     g_stats[40 + 16 + i * 3 + 2]) * (1.0f / (3.0f * N_NODES));
        r = pre * rsqrtf(nrm + 1e-5f) * bnwv[i];
    }
    out[t] = r;
}

// ---------------- passthrough copy of edge_features ----------------
__global__ void k_copyef(const float* __restrict__ ef, float* __restrict__ out) {
    int t = blockIdx.x * 256 + threadIdx.x;
    if (t >= (N_EDGES * 32) / 4) return;
    ((float4*)out)[t] = ((const float4*)ef)[t];
}

// ---------------- launch ----------------
extern "C" void kernel_launch(void* const* d_in, const int* in_sizes, int n_in,
                              void* d_out, int out_size) {
    const float* atom = (const float*)d_in[0];
    const float* ef   = (const float*)d_in[1];
    const float* sh   = (const float*)d_in[2];
    const float* Wq_s = (const float*)d_in[3];
    const float* Wq_v = (const float*)d_in[4];
    const float* kw1  = (const float*)d_in[5];
    const float* kb1  = (const float*)d_in[6];
    const float* kw2  = (const float*)d_in[7];
    const float* kb2  = (const float*)d_in[8];
    const float* vw1  = (const float*)d_in[9];
    const float* vb1  = (const float*)d_in[10];
    const float* vw2  = (const float*)d_in[11];
    const float* vb2  = (const float*)d_in[12];
    const float* bnws = (const float*)d_in[13];
    const float* bnbs = (const float*)d_in[14];
    const float* bnwv = (const float*)d_in[15];
    const int*   eidx = (const int*)d_in[16];
    float* out = (float*)d_out;

    cudaFuncSetAttribute(k_edges, cudaFuncAttributeMaxDynamicSharedMemorySize, SMEM_BYTES);

    k_init<<<(40 * N_NODES + 255) / 256, 256>>>();
    k_transpose<<<(WN * 32 + 255) / 256, 256>>>(kw2, vw2);
    k_q<<<(40 * N_NODES + 255) / 256, 256>>>(atom, Wq_s, Wq_v);
    k_edges<<<(N_EDGES + 127) / 128, 128, SMEM_BYTES>>>(atom, ef, sh, eidx,
                                                        kw1, kb1, kb2, vw1, vb1, vb2);
    k_soft<<<(N_EDGES + 255) / 256, 256>>>(eidx);
    dim3 gs((N_NODES + 255) / 256, 40);
    k_stats<<<gs, 256>>>(atom);
    k_final<<<(40 * N_NODES + 255) / 256, 256>>>(bnws, bnbs, bnwv, out);
    k_copyef<<<((N_EDGES * 32) / 4 + 255) / 256, 256>>>(ef, out + 40 * N_NODES);
}

// round 2
// speedup vs baseline: 1.2044x; 1.2044x over previous
#include <cuda_runtime.h>
#include <math.h>

#define N_NODES 10000
#define N_EDGES 160000
#define WN 640
#define C110 0.57735026918962576451f   /* 1/sqrt(3) */
#define C111 0.70710678118654752440f   /* 1/sqrt(2) */

typedef unsigned long long u64;

// ---------------- device scratch (no runtime allocation allowed) ----------------
__device__ float g_W2kT[WN * 32];
__device__ float g_W2vT[WN * 32];
__device__ float g_q[N_NODES * 40];
__device__ float g_attn[N_EDGES];
__device__ float g_vT[40 * (size_t)N_EDGES];
__device__ int   g_m[N_NODES];
__device__ float g_denom[N_NODES];
__device__ float g_numer[40 * N_NODES];
__device__ float g_pre[40 * N_NODES];
__device__ float g_stats[80];

// ---------------- packed f32x2 helpers ----------------
__device__ __forceinline__ u64 fma2(u64 a, u64 b, u64 c) {
    u64 d;
    asm("fma.rn.f32x2 %0, %1, %2, %3;" : "=l"(d) : "l"(a), "l"(b), "l"(c));
    return d;
}
__device__ __forceinline__ u64 pack2(float lo, float hi) {
    u64 r;
    asm("mov.b64 %0, {%1, %2};" : "=l"(r) : "f"(lo), "f"(hi));
    return r;
}
__device__ __forceinline__ float sum2(u64 v) {
    float a, b;
    asm("mov.b64 {%0, %1}, %2;" : "=f"(a), "=f"(b) : "l"(v));
    return a + b;
}

// monotone float<->int key for atomicMax
__device__ __forceinline__ int fkey(float f) {
    int b = __float_as_int(f);
    return (b >= 0) ? b : (int)(b ^ 0x7FFFFFFF);
}
__device__ __forceinline__ float fdec(int k) {
    return (k >= 0) ? __int_as_float(k) : __int_as_float((int)(k ^ 0x7FFFFFFF));
}

// ---------------- prep kernels ----------------
__global__ void k_init() {
    int i = blockIdx.x * 256 + threadIdx.x;
    if (i < 40 * N_NODES) g_numer[i] = 0.0f;
    if (i < N_NODES) { g_denom[i] = 0.0f; g_m[i] = (int)0x807FFFFFu; /* key(-inf) */ }
    if (i < 80) g_stats[i] = 0.0f;
}

__global__ void k_transpose(const float* __restrict__ kw2, const float* __restrict__ vw2) {
    int i = blockIdx.x * 256 + threadIdx.x;
    if (i < WN * 32) {
        int j = i / WN, c = i % WN;
        g_W2kT[c * 32 + j] = kw2[i];
        g_W2vT[c * 32 + j] = vw2[i];
    }
}

__global__ void k_q(const float* __restrict__ atom, const float* __restrict__ Wqs,
                    const float* __restrict__ Wqv) {
    int t = blockIdx.x * 256 + threadIdx.x;
    if (t >= 40 * N_NODES) return;
    int n = t / 40, f = t % 40;
    const float* a = atom + (size_t)n * 40;
    float acc = 0.0f;
    if (f < 16) {
#pragma unroll
        for (int i = 0; i < 16; i++) acc = fmaf(a[i], Wqs[i * 16 + f], acc);
    } else {
        int o = (f - 16) / 3, d = (f - 16) % 3;
#pragma unroll
        for (int i = 0; i < 8; i++) acc = fmaf(a[16 + i * 3 + d], Wqv[i * 8 + o], acc);
    }
    g_q[t] = acc;
}

// ---------------- fused per-edge kernel helpers ----------------
// MLP layer 1, k-paired f32x2: ef2 = packed pairs of the 32 edge features.
__device__ __forceinline__ void mlp1p(const float* __restrict__ sW1T,
                                      const float* __restrict__ sB1,
                                      const u64 (&ef2)[16], u64 (&h2)[16]) {
    float h[32];
#pragma unroll
    for (int l = 0; l < 32; l++) {
        u64 acc = 0ull;
        const ulonglong2* w = (const ulonglong2*)(sW1T + l * 32);
#pragma unroll
        for (int j = 0; j < 8; j++) {
            ulonglong2 ww = w[j];
            acc = fma2(ef2[2 * j], ww.x, acc);
            acc = fma2(ef2[2 * j + 1], ww.y, acc);
        }
        h[l] = fmaxf(sum2(acc) + sB1[l], 0.0f);
    }
#pragma unroll
    for (int j = 0; j < 16; j++) h2[j] = pack2(h[2 * j], h[2 * j + 1]);
}

// NC output columns of the 640-wide GEMM, k-paired f32x2.
template <int NC>
__device__ __forceinline__ void gemm_cols2(const float* __restrict__ w2blk,
                                           const float* __restrict__ b2blk,
                                           const u64 (&h2)[16], float (&out)[NC]) {
#pragma unroll
    for (int o = 0; o < NC; o++) {
        u64 acc = 0ull;
        const ulonglong2* w = (const ulonglong2*)(w2blk + o * 32);
#pragma unroll
        for (int j = 0; j < 8; j++) {
            ulonglong2 ww = w[j];
            acc = fma2(h2[2 * j], ww.x, acc);
            acc = fma2(h2[2 * j + 1], ww.y, acc);
        }
        out[o] = sum2(acc) + b2blk[o];
    }
}

// Fused MLP2-GEMM + tensor-product fold. Never materializes the 640-vector.
__device__ __forceinline__ void tp_apply(const float* __restrict__ sW2,
                                         const float* __restrict__ sB2,
                                         const u64 (&h2)[16],
                                         const float* __restrict__ cxs,  // smem: [0..15]=x_s, [16..23]=C110*dot
                                         float sh_s, float s0, float s1, float s2,
                                         const float (&xv)[24], const float (&crs)[24],
                                         float (&os)[16], float (&ov)[24]) {
    // block1: w1[16x16] with coef x_s[i]*sh_s -> out_s
#pragma unroll 1
    for (int i = 0; i < 16; i++) {
        float acc[16];
        gemm_cols2<16>(sW2 + (i * 16) * 32, sB2 + i * 16, h2, acc);
        float ci = cxs[i] * sh_s;
#pragma unroll
        for (int o = 0; o < 16; o++) os[o] = fmaf(ci, acc[o], os[o]);
    }
    // block2: w2[8x16] with coef C110*dot[i] -> out_s
#pragma unroll 1
    for (int i = 0; i < 8; i++) {
        float acc[16];
        gemm_cols2<16>(sW2 + (256 + i * 16) * 32, sB2 + 256 + i * 16, h2, acc);
        float ci = cxs[16 + i];
#pragma unroll
        for (int o = 0; o < 16; o++) os[o] = fmaf(ci, acc[o], os[o]);
    }
    // block3: w3[16x8], out_v[o][d] += w*x_s[i]*sh_v[d]
#pragma unroll 1
    for (int i = 0; i < 16; i++) {
        float acc[8];
        gemm_cols2<8>(sW2 + (384 + i * 8) * 32, sB2 + 384 + i * 8, h2, acc);
        float ci = cxs[i];
#pragma unroll
        for (int o = 0; o < 8; o++) {
            float t = ci * acc[o];
            ov[o * 3 + 0] = fmaf(t, s0, ov[o * 3 + 0]);
            ov[o * 3 + 1] = fmaf(t, s1, ov[o * 3 + 1]);
            ov[o * 3 + 2] = fmaf(t, s2, ov[o * 3 + 2]);
        }
    }
    // block4: w4[8x8], out_v[o][d] += w*sh_s*x_v[i][d]  (i unrolled: xv stays in regs)
#pragma unroll
    for (int i = 0; i < 8; i++) {
        float acc[8];
        gemm_cols2<8>(sW2 + (512 + i * 8) * 32, sB2 + 512 + i * 8, h2, acc);
#pragma unroll
        for (int o = 0; o < 8; o++) {
            float t = sh_s * acc[o];
            ov[o * 3 + 0] = fmaf(t, xv[i * 3 + 0], ov[o * 3 + 0]);
            ov[o * 3 + 1] = fmaf(t, xv[i * 3 + 1], ov[o * 3 + 1]);
            ov[o * 3 + 2] = fmaf(t, xv[i * 3 + 2], ov[o * 3 + 2]);
        }
    }
    // block5: w5[8x8], out_v[o][d] += w*C111*cross[i][d]
#pragma unroll
    for (int i = 0; i < 8; i++) {
        float acc[8];
        gemm_cols2<8>(sW2 + (576 + i * 8) * 32, sB2 + 576 + i * 8, h2, acc);
#pragma unroll
        for (int o = 0; o < 8; o++) {
            float a = acc[o];
            ov[o * 3 + 0] = fmaf(a, crs[i * 3 + 0], ov[o * 3 + 0]);
            ov[o * 3 + 1] = fmaf(a, crs[i * 3 + 1], ov[o * 3 + 1]);
            ov[o * 3 + 2] = fmaf(a, crs[i * 3 + 2], ov[o * 3 + 2]);
        }
    }
}

// smem layout (floats)
#define SM_W2    0
#define SM_W1K   20480
#define SM_W1V   (SM_W1K + 1024)
#define SM_B1K   (SM_W1V + 1024)
#define SM_B1V   (SM_B1K + 32)
#define SM_B2K   (SM_B1V + 32)
#define SM_B2V   (SM_B2K + 640)
#define SM_COEF  (SM_B2V + 640)
#define SM_TOTAL (SM_COEF + 128 * 25)
#define SMEM_BYTES (SM_TOTAL * 4)

__device__ __forceinline__ void load_ef2(const float* __restrict__ ef_g, int ee, u64 (&ef2)[16]) {
    const float4* p = (const float4*)(ef_g + (size_t)ee * 32);
#pragma unroll
    for (int i = 0; i < 8; i++) {
        float4 v = __ldg(p + i);
        ef2[2 * i + 0] = pack2(v.x, v.y);
        ef2[2 * i + 1] = pack2(v.z, v.w);
    }
}

__global__ __launch_bounds__(128, 2) void k_edges(
    const float* __restrict__ atom, const float* __restrict__ ef_g,
    const float* __restrict__ sh_g, const int* __restrict__ eidx,
    const float* __restrict__ kw1, const float* __restrict__ kb1, const float* __restrict__ kb2,
    const float* __restrict__ vw1, const float* __restrict__ vb1, const float* __restrict__ vb2) {
    extern __shared__ float sm[];
    float* sW2 = sm + SM_W2;
    float* sW1k = sm + SM_W1K;
    float* sW1v = sm + SM_W1V;
    float* sB1k = sm + SM_B1K;
    float* sB1v = sm + SM_B1V;
    float* sB2k = sm + SM_B2K;
    float* sB2v = sm + SM_B2V;
    float* sCoef = sm + SM_COEF;
    int tid = threadIdx.x;

    // stage W1 (transposed in-flight) + biases
    for (int i = tid; i < 1024; i += 128) {
        sW1k[(i % 32) * 32 + (i / 32)] = kw1[i];
        sW1v[(i % 32) * 32 + (i / 32)] = vw1[i];
    }
    for (int i = tid; i < 640; i += 128) { sB2k[i] = kb2[i]; sB2v[i] = vb2[i]; }
    if (tid < 32) { sB1k[tid] = kb1[tid]; sB1v[tid] = vb1[tid]; }
    // stage W2k^T
    {
        const float4* src = (const float4*)g_W2kT;
        float4* dst = (float4*)sW2;
        for (int i = tid; i < WN * 8; i += 128) dst[i] = src[i];
    }
    __syncthreads();

    int e = blockIdx.x * 128 + tid;
    bool valid = (e < N_EDGES);
    int ee = valid ? e : 0;

    u64 h2[16];
    {
        u64 ef2[16];
        load_ef2(ef_g, ee, ef2);
        mlp1p(sW1k, sB1k, ef2, h2);
    }

    int dst_n = __ldg(eidx + ee);
    int src_n = __ldg(eidx + N_EDGES + ee);
    float4 sh4 = __ldg(((const float4*)sh_g) + ee);
    float sh_s = sh4.x, s0 = sh4.y, s1 = sh4.z, s2 = sh4.w;

    // gather destination node irreps, build TP coefficients
    float xf[40];
    {
        const float4* p = (const float4*)(atom + (size_t)dst_n * 40);
#pragma unroll
        for (int i = 0; i < 10; i++) {
            float4 v = __ldg(p + i);
            xf[4 * i + 0] = v.x; xf[4 * i + 1] = v.y; xf[4 * i + 2] = v.z; xf[4 * i + 3] = v.w;
        }
    }
    float* cx = sCoef + tid * 25;
#pragma unroll
    for (int i = 0; i < 16; i++) cx[i] = xf[i];
    float xv[24], crs[24];
#pragma unroll
    for (int i = 0; i < 8; i++) {
        float a0 = xf[16 + i * 3 + 0], a1 = xf[16 + i * 3 + 1], a2 = xf[16 + i * 3 + 2];
        xv[i * 3 + 0] = a0; xv[i * 3 + 1] = a1; xv[i * 3 + 2] = a2;
        cx[16 + i] = C110 * (a0 * s0 + a1 * s1 + a2 * s2);
        crs[i * 3 + 0] = C111 * (a1 * s2 - a2 * s1);
        crs[i * 3 + 1] = C111 * (a2 * s0 - a0 * s2);
        crs[i * 3 + 2] = C111 * (a0 * s1 - a1 * s0);
    }

    // ---- k path ----
    float os[16], ov[24];
#pragma unroll
    for (int o = 0; o < 16; o++) os[o] = 0.0f;
#pragma unroll
    for (int t = 0; t < 24; t++) ov[t] = 0.0f;
    tp_apply(sW2, sB2k, h2, cx, sh_s, s0, s1, s2, xv, crs, os, ov);

    float attn = 0.0f;
    {
        const float4* q = (const float4*)(g_q + (size_t)src_n * 40);
        float qv[40];
#pragma unroll
        for (int i = 0; i < 10; i++) {
            float4 v = __ldg(q + i);
            qv[4 * i + 0] = v.x; qv[4 * i + 1] = v.y; qv[4 * i + 2] = v.z; qv[4 * i + 3] = v.w;
        }
#pragma unroll
        for (int o = 0; o < 16; o++) attn = fmaf(os[o], qv[o], attn);
#pragma unroll
        for (int t = 0; t < 24; t++) attn = fmaf(ov[t], qv[16 + t], attn);
    }
    if (valid) {
        g_attn[e] = attn;
        atomicMax(&g_m[src_n], fkey(attn));
    }

    // ---- v path (restage W2v^T, recompute mlp1 to keep registers low) ----
    __syncthreads();
    {
        const float4* src = (const float4*)g_W2vT;
        float4* dst = (float4*)sW2;
        for (int i = tid; i < WN * 8; i += 128) dst[i] = src[i];
    }
    __syncthreads();
    {
        u64 ef2[16];
        load_ef2(ef_g, ee, ef2);
        mlp1p(sW1v, sB1v, ef2, h2);
    }
#pragma unroll
    for (int o = 0; o < 16; o++) os[o] = 0.0f;
#pragma unroll
    for (int t = 0; t < 24; t++) ov[t] = 0.0f;
    tp_apply(sW2, sB2v, h2, cx, sh_s, s0, s1, s2, xv, crs, os, ov);

    if (valid) {
#pragma unroll
        for (int o = 0; o < 16; o++) g_vT[(size_t)o * N_EDGES + e] = os[o];
#pragma unroll
        for (int t = 0; t < 24; t++) g_vT[(size_t)(16 + t) * N_EDGES + e] = ov[t];
    }
}

// ---------------- softmax accumulation ----------------
__global__ void k_soft(const int* __restrict__ eidx) {
    int e = blockIdx.x * 256 + threadIdx.x;
    if (e >= N_EDGES) return;
    int src = eidx[N_EDGES + e];
    float m = fdec(g_m[src]);
    float ex = expf(g_attn[e] - m);
    atomicAdd(&g_denom[src], ex);
#pragma unroll
    for (int f = 0; f < 40; f++) {
        atomicAdd(&g_numer[f * N_NODES + src], ex * g_vT[(size_t)f * N_EDGES + e]);
    }
}

// ---------------- pre-activation + batchnorm stats ----------------
__global__ void k_stats(const float* __restrict__ atom) {
    int f = blockIdx.y;
    int n = blockIdx.x * 256 + threadIdx.x;
    float pre = 0.0f;
    if (n < N_NODES) {
        float den = g_denom[n];
        float upd = (den > 0.0f) ? g_numer[f * N_NODES + n] / den : 0.0f;
        pre = atom[(size_t)n * 40 + f] + upd;
        g_pre[f * N_NODES + n] = pre;
    }
    float s = pre, ss = pre * pre;
    unsigned lane = threadIdx.x & 31, wid = threadIdx.x >> 5;
#pragma unroll
    for (int o = 16; o > 0; o >>= 1) {
        s += __shfl_down_sync(0xFFFFFFFFu, s, o);
        ss += __shfl_down_sync(0xFFFFFFFFu, ss, o);
    }
    __shared__ float rs[8], rss[8];
    if (lane == 0) { rs[wid] = s; rss[wid] = ss; }
    __syncthreads();
    if (threadIdx.x == 0) {
        float S = 0.0f, SS = 0.0f;
#pragma unroll
        for (int w = 0; w < 8; w++) { S += rs[w]; SS += rss[w]; }
        atomicAdd(&g_stats[f], S);
        atomicAdd(&g_stats[40 + f], SS);
    }
}

// ---------------- batchnorm finalize ----------------
__global__ void k_final(const float* __restrict__ bnws, const float* __restrict__ bnbs,
                        const float* __restrict__ bnwv, float* __restrict__ out) {
    int t = blockIdx.x * 256 + threadIdx.x;
    if (t >= 40 * N_NODES) return;
    int n = t / 40, f = t % 40;
    float pre = g_pre[f * N_NODES + n];
    float r;
    if (f < 16) {
        float mu = g_stats[f] * (1.0f / N_NODES);
        float var = g_stats[40 + f] * (1.0f / N_NODES) - mu * mu;
        r = (pre - mu) * rsqrtf(var + 1e-5f) * bnws[f] + bnbs[f];
    } else {
        int i = (f - 16) / 3;
        float nrm = (g_stats[40 + 16 + i * 3 + 0] + g_stats[40 + 16 + i * 3 + 1] +
                     g_stats[40 + 16 + i * 3 + 2]) * (1.0f / (3.0f * N_NODES));
        r = pre * rsqrtf(nrm + 1e-5f) * bnwv[i];
    }
    out[t] = r;
}

// ---------------- passthrough copy of edge_features ----------------
__global__ void k_copyef(const float* __restrict__ ef, float* __restrict__ out) {
    int t = blockIdx.x * 256 + threadIdx.x;
    if (t >= (N_EDGES * 32) / 4) return;
    ((float4*)out)[t] = ((const float4*)ef)[t];
}

// ---------------- launch ----------------
extern "C" void kernel_launch(void* const* d_in, const int* in_sizes, int n_in,
                              void* d_out, int out_size) {
    const float* atom = (const float*)d_in[0];
    const float* ef   = (const float*)d_in[1];
    const float* sh   = (const float*)d_in[2];
    const float* Wq_s = (const float*)d_in[3];
    const float* Wq_v = (const float*)d_in[4];
    const float* kw1  = (const float*)d_in[5];
    const float* kb1  = (const float*)d_in[6];
    const float* kw2  = (const float*)d_in[7];
    const float* kb2  = (const float*)d_in[8];
    const float* vw1  = (const float*)d_in[9];
    const float* vb1  = (const float*)d_in[10];
    const float* vw2  = (const float*)d_in[11];
    const float* vb2  = (const float*)d_in[12];
    const float* bnws = (const float*)d_in[13];
    const float* bnbs = (const float*)d_in[14];
    const float* bnwv = (const float*)d_in[15];
    const int*   eidx = (const int*)d_in[16];
    float* out = (float*)d_out;

    cudaFuncSetAttribute(k_edges, cudaFuncAttributeMaxDynamicSharedMemorySize, SMEM_BYTES);

    k_init<<<(40 * N_NODES + 255) / 256, 256>>>();
    k_transpose<<<(WN * 32 + 255) / 256, 256>>>(kw2, vw2);
    k_q<<<(40 * N_NODES + 255) / 256, 256>>>(atom, Wq_s, Wq_v);
    k_edges<<<(N_EDGES + 127) / 128, 128, SMEM_BYTES>>>(atom, ef, sh, eidx,
                                                        kw1, kb1, kb2, vw1, vb1, vb2);
    k_soft<<<(N_EDGES + 255) / 256, 256>>>(eidx);
    dim3 gs((N_NODES + 255) / 256, 40);
    k_stats<<<gs, 256>>>(atom);
    k_final<<<(40 * N_NODES + 255) / 256, 256>>>(bnws, bnbs, bnwv, out);
    k_copyef<<<((N_EDGES * 32) / 4 + 255) / 256, 256>>>(ef, out + 40 * N_NODES);
}